// round 1
// baseline (speedup 1.0000x reference)
#include <cuda_runtime.h>
#include <math.h>

// Problem constants
#define BB   8
#define TT   64
#define NN   256
#define HH   256
#define DIN  6
#define DOUT 9
#define H3   768
#define ROWS_PER_TILE 16
#define TILES (NN / ROWS_PER_TILE)   // 16

// ---------------------------------------------------------------------------
// Device scratch (no allocations allowed)
// ---------------------------------------------------------------------------
__device__ float g_h0 [BB * NN * HH];   // layer-0 hidden state  [2048,256]
__device__ float g_h1 [BB * NN * HH];   // layer-1 hidden state
__device__ float g_z  [BB * NN * HH];   // update gate (current layer/step)
__device__ float g_rh [BB * NN * HH];   // r * h
__device__ float g_gxc[BB * NN * HH];   // candidate-part of gx
__device__ int   g_rowptr[NN + 1];
__device__ int   g_colidx[NN * NN];
__device__ float g_aval  [NN * NN];

// ---------------------------------------------------------------------------
// Prologue: build CSR of s_adj (deterministic, rebuilt every call)
// ---------------------------------------------------------------------------
__global__ void build_csr(const float* __restrict__ A)
{
    __shared__ int cnt[NN];
    const int n = threadIdx.x;            // one thread per row, 256 threads
    int c = 0;
    for (int m = 0; m < NN; ++m)
        if (A[n * NN + m] != 0.0f) ++c;
    cnt[n] = c;
    __syncthreads();
    if (n == 0) {
        int s = 0;
        for (int i = 0; i < NN; ++i) { g_rowptr[i] = s; s += cnt[i]; }
        g_rowptr[NN] = s;
    }
    __syncthreads();
    int off = g_rowptr[n];
    for (int m = 0; m < NN; ++m) {
        float v = A[n * NN + m];
        if (v != 0.0f) { g_colidx[off] = m; g_aval[off] = v; ++off; }
    }
}

__global__ void zero_state()
{
    int i = blockIdx.x * blockDim.x + threadIdx.x;
    const int total = BB * NN * HH;
    for (; i < total; i += gridDim.x * blockDim.x) {
        g_h0[i] = 0.0f;
        g_h1[i] = 0.0f;
    }
}

// ---------------------------------------------------------------------------
// Sparse A @ src for a 16-row tile -> SMEM S[16][256]
// src rows indexed by (b*256 + col), 256 floats each.
// warp w handles rows 2w, 2w+1; lane covers float4 [lane] and [lane+32].
// ---------------------------------------------------------------------------
__device__ __forceinline__ void spmm16(float* S, const float* __restrict__ src,
                                       int b, int rows0)
{
    const int warp = threadIdx.x >> 5;
    const int lane = threadIdx.x & 31;
#pragma unroll
    for (int rr = 0; rr < 2; ++rr) {
        const int r    = (warp << 1) + rr;
        const int node = rows0 + r;
        const int p0 = g_rowptr[node];
        const int p1 = g_rowptr[node + 1];
        float4 a0 = make_float4(0.f, 0.f, 0.f, 0.f);
        float4 a1 = make_float4(0.f, 0.f, 0.f, 0.f);
        for (int p = p0; p < p1; ++p) {
            const int   c = g_colidx[p];
            const float v = g_aval[p];
            const float4* srow =
                reinterpret_cast<const float4*>(src + ((b << 8) + c) * HH);
            const float4 s0 = srow[lane];
            const float4 s1 = srow[lane + 32];
            a0.x += v * s0.x; a0.y += v * s0.y; a0.z += v * s0.z; a0.w += v * s0.w;
            a1.x += v * s1.x; a1.y += v * s1.y; a1.z += v * s1.z; a1.w += v * s1.w;
        }
        float4* Sp = reinterpret_cast<float4*>(S + (r << 8));
        Sp[lane]      = a0;
        Sp[lane + 32] = a1;
    }
}

// ---------------------------------------------------------------------------
// Gates kernel: computes z, r*h, gx_c for one layer at timestep t.
//   gzr = (A x)@Wx[:, :512] + b[:512] + (A h)@Wh[:, :512]
//   z = sigmoid(gzr[:,:256]); r = sigmoid(gzr[:,256:512]); rh = r*h
//   gxc = (A x)@Wx[:, 512:768] + b[512:]
// LAYER==0: x = masked input (K=6). LAYER==1: x = g_h0 (K=256).
// Grid: (16 tiles, 8 batches), 256 threads.
// ---------------------------------------------------------------------------
template <int LAYER>
__global__ void __launch_bounds__(256)
gru_gates(const float* __restrict__ x2d, const float* __restrict__ mask,
          const float* __restrict__ Wx,  const float* __restrict__ Wh,
          const float* __restrict__ bias, int t)
{
    __shared__ __align__(16) float AhS[ROWS_PER_TILE * HH];
    __shared__ __align__(16) float AxS[ROWS_PER_TILE * HH];

    const int b     = blockIdx.y;
    const int rows0 = blockIdx.x * ROWS_PER_TILE;
    const float* h  = (LAYER == 0) ? g_h0 : g_h1;

    // ---- sparse phase ----
    spmm16(AhS, h, b, rows0);
    if (LAYER == 1) {
        spmm16(AxS, g_h0, b, rows0);
    } else {
        const int tid = threadIdx.x;
        if (tid < ROWS_PER_TILE * DIN) {
            const int r = tid / DIN, d = tid % DIN;
            const int node = rows0 + r;
            const float* xt = x2d + (size_t)((b * TT + t) * NN) * DIN;
            const float* mt = mask + (size_t)(b * TT + t) * NN;
            float acc = 0.0f;
            const int p1 = g_rowptr[node + 1];
            for (int p = g_rowptr[node]; p < p1; ++p) {
                const int c = g_colidx[p];
                acc += g_aval[p] * xt[c * DIN + d] * mt[c];
            }
            AxS[r * HH + d] = acc;
        }
    }
    __syncthreads();

    // ---- dense phase: 3 column passes of 256 (z | r | gxc) ----
    const int tr = threadIdx.x >> 6;   // 0..3 : row group
    const int tc = threadIdx.x & 63;   // 0..63: col group (4 cols)
    const int r0 = tr << 2;

    for (int pass = 0; pass < 3; ++pass) {
        const int cb = pass << 8;
        float acc[4][4];
        {
            const float4 bv =
                *reinterpret_cast<const float4*>(bias + cb + (tc << 2));
#pragma unroll
            for (int i = 0; i < 4; ++i) {
                acc[i][0] = bv.x; acc[i][1] = bv.y;
                acc[i][2] = bv.z; acc[i][3] = bv.w;
            }
        }

        // x-path (all 3 passes)
        {
            const float* Wp = Wx + cb + (tc << 2);
            const int KX = (LAYER == 1) ? HH : DIN;
#pragma unroll 4
            for (int k = 0; k < KX; ++k) {
                const float4 w = *reinterpret_cast<const float4*>(Wp + k * H3);
#pragma unroll
                for (int i = 0; i < 4; ++i) {
                    const float s = AxS[(r0 + i) * HH + k];
                    acc[i][0] += s * w.x; acc[i][1] += s * w.y;
                    acc[i][2] += s * w.z; acc[i][3] += s * w.w;
                }
            }
        }
        // h-path (only gzr passes)
        if (pass < 2) {
            const float* Wp = Wh + cb + (tc << 2);
#pragma unroll 4
            for (int k = 0; k < HH; ++k) {
                const float4 w = *reinterpret_cast<const float4*>(Wp + k * H3);
#pragma unroll
                for (int i = 0; i < 4; ++i) {
                    const float s = AhS[(r0 + i) * HH + k];
                    acc[i][0] += s * w.x; acc[i][1] += s * w.y;
                    acc[i][2] += s * w.z; acc[i][3] += s * w.w;
                }
            }
        }

        // epilogue
#pragma unroll
        for (int i = 0; i < 4; ++i) {
            const int row  = rows0 + r0 + i;
            const int base = ((b << 8) + row) << 8;      // *HH
#pragma unroll
            for (int j = 0; j < 4; ++j) {
                const int col = (tc << 2) + j;
                const float g = acc[i][j];
                if (pass == 0) {
                    g_z[base + col] = 1.0f / (1.0f + __expf(-g));
                } else if (pass == 1) {
                    const float r  = 1.0f / (1.0f + __expf(-g));
                    g_rh[base + col] = r * h[base + col];
                } else {
                    g_gxc[base + col] = g;
                }
            }
        }
    }
}

// ---------------------------------------------------------------------------
// Update kernel: c = tanh(gxc + (A rh)@Wh[:,512:768]); h = z*h + (1-z)*c.
// LAYER==1 additionally computes the output head y = h1@Wout + bout.
// ---------------------------------------------------------------------------
template <int LAYER>
__global__ void __launch_bounds__(256)
gru_update(const float* __restrict__ Wh, const float* __restrict__ Wout,
           const float* __restrict__ bout, float* __restrict__ out, int t)
{
    __shared__ __align__(16) float ArS[ROWS_PER_TILE * HH];
    __shared__ __align__(16) float HS [ROWS_PER_TILE * HH];

    const int b     = blockIdx.y;
    const int rows0 = blockIdx.x * ROWS_PER_TILE;
    float* h = (LAYER == 0) ? g_h0 : g_h1;

    spmm16(ArS, g_rh, b, rows0);
    __syncthreads();

    const int tr = threadIdx.x >> 6;
    const int tc = threadIdx.x & 63;
    const int r0 = tr << 2;

    float acc[4][4];
#pragma unroll
    for (int i = 0; i < 4; ++i)
#pragma unroll
        for (int j = 0; j < 4; ++j) acc[i][j] = 0.0f;

    const float* Wp = Wh + 512 + (tc << 2);
#pragma unroll 4
    for (int k = 0; k < HH; ++k) {
        const float4 w = *reinterpret_cast<const float4*>(Wp + k * H3);
#pragma unroll
        for (int i = 0; i < 4; ++i) {
            const float s = ArS[(r0 + i) * HH + k];
            acc[i][0] += s * w.x; acc[i][1] += s * w.y;
            acc[i][2] += s * w.z; acc[i][3] += s * w.w;
        }
    }

#pragma unroll
    for (int i = 0; i < 4; ++i) {
        const int row  = rows0 + r0 + i;
        const int base = ((b << 8) + row) << 8;
#pragma unroll
        for (int j = 0; j < 4; ++j) {
            const int col = (tc << 2) + j;
            const int idx = base + col;
            const float c  = tanhf(g_gxc[idx] + acc[i][j]);
            const float z  = g_z[idx];
            const float hn = z * h[idx] + (1.0f - z) * c;
            h[idx] = hn;
            if (LAYER == 1) HS[(r0 + i) * HH + col] = hn;
        }
    }

    if (LAYER == 1) {
        __syncthreads();
        // head: y[16 rows][9] = HS @ Wout + bout
        for (int idx = threadIdx.x; idx < ROWS_PER_TILE * DOUT; idx += 256) {
            const int row = idx / DOUT, c9 = idx % DOUT;
            float a = bout[c9];
            const float* hrow = HS + row * HH;
#pragma unroll 8
            for (int k = 0; k < HH; ++k)
                a += hrow[k] * Wout[k * DOUT + c9];
            const int node = rows0 + row;
            out[(size_t)((b * TT + t) * NN + node) * DOUT + c9] = a;
        }
    }
}

// ---------------------------------------------------------------------------
// Launch: 2 prologue + 64 steps x (gates0, update0, gates1, update1)
// ---------------------------------------------------------------------------
extern "C" void kernel_launch(void* const* d_in, const int* in_sizes, int n_in,
                              void* d_out, int out_size)
{
    const float* x2d  = (const float*)d_in[0];
    const float* mask = (const float*)d_in[1];
    const float* sadj = (const float*)d_in[2];
    const float* Wx0  = (const float*)d_in[3];
    const float* Wh0  = (const float*)d_in[4];
    const float* b0   = (const float*)d_in[5];
    const float* Wx1  = (const float*)d_in[6];
    const float* Wh1  = (const float*)d_in[7];
    const float* b1   = (const float*)d_in[8];
    const float* Wout = (const float*)d_in[9];
    const float* bout = (const float*)d_in[10];
    float* out = (float*)d_out;

    build_csr<<<1, 256>>>(sadj);
    zero_state<<<256, 256>>>();

    dim3 grid(TILES, BB);
    for (int t = 0; t < TT; ++t) {
        gru_gates<0><<<grid, 256>>>(x2d, mask, Wx0, Wh0, b0, t);
        gru_update<0><<<grid, 256>>>(Wh0, Wout, bout, out, t);
        gru_gates<1><<<grid, 256>>>(x2d, mask, Wx1, Wh1, b1, t);
        gru_update<1><<<grid, 256>>>(Wh1, Wout, bout, out, t);
    }
}

// round 3
// speedup vs baseline: 1.3840x; 1.3840x over previous
#include <cuda_runtime.h>
#include <math.h>
#include <stdint.h>

// Problem constants
#define BB   8
#define TT   64
#define NN   256
#define HH   256
#define DIN  6
#define DOUT 9
#define H3   768
#define RPT  16                 // rows (nodes) per CTA tile
#define TILES (NN / RPT)        // 16
#define KT   32                 // K-tile depth for weight streaming
#define WBUF (KT * 256)         // floats per weight buffer (8192)

typedef unsigned long long ull;

// ---------------------------------------------------------------------------
// Device scratch (no allocations allowed)
// ---------------------------------------------------------------------------
__device__ float g_h0 [BB * NN * HH];
__device__ float g_h1 [BB * NN * HH];
__device__ float g_z  [BB * NN * HH];
__device__ float g_rh [BB * NN * HH];
__device__ float g_gxc[BB * NN * HH];
__device__ int   g_rowptr[NN + 1];
__device__ int   g_colidx[NN * NN];
__device__ float g_aval  [NN * NN];

// ---------------------------------------------------------------------------
// Helpers: packed f32x2 FMA, cp.async
// ---------------------------------------------------------------------------
__device__ __forceinline__ ull pk2(float x, float y) {
    float2 t = make_float2(x, y);
    return *reinterpret_cast<ull*>(&t);
}
__device__ __forceinline__ float2 upk2(ull u) {
    return *reinterpret_cast<float2*>(&u);
}
__device__ __forceinline__ void ffma2(ull& c, ull a, ull b) {
    asm("fma.rn.f32x2 %0, %1, %2, %0;" : "+l"(c) : "l"(a), "l"(b));
}
__device__ __forceinline__ uint32_t sptr(const void* p) {
    return (uint32_t)__cvta_generic_to_shared(p);
}
__device__ __forceinline__ void cp16(uint32_t s, const void* g) {
    asm volatile("cp.async.ca.shared.global [%0], [%1], 16;" :: "r"(s), "l"(g));
}
#define CP_COMMIT() asm volatile("cp.async.commit_group;")
#define CP_WAIT1()  asm volatile("cp.async.wait_group 1;")
#define CP_WAIT0()  asm volatile("cp.async.wait_group 0;")

// Load one weight K-tile [KT][256] (row stride H3 in global) into smem buf.
__device__ __forceinline__ void load_wtile(float* buf, const float* __restrict__ src,
                                           int tid) {
#pragma unroll
    for (int i = 0; i < 8; ++i) {
        const int f   = tid + (i << 8);      // float4 index 0..2047
        const int row = f >> 6;
        const int c4  = f & 63;
        cp16(sptr(buf + row * 256 + (c4 << 2)), src + row * H3 + (c4 << 2));
    }
    CP_COMMIT();
}

// ---------------------------------------------------------------------------
// Prologue kernels
// ---------------------------------------------------------------------------
__global__ void build_csr(const float* __restrict__ A)
{
    __shared__ int cnt[NN];
    const int n = threadIdx.x;
    int c = 0;
    for (int m = 0; m < NN; ++m)
        if (A[n * NN + m] != 0.0f) ++c;
    cnt[n] = c;
    __syncthreads();
    if (n == 0) {
        int s = 0;
        for (int i = 0; i < NN; ++i) { g_rowptr[i] = s; s += cnt[i]; }
        g_rowptr[NN] = s;
    }
    __syncthreads();
    int off = g_rowptr[n];
    for (int m = 0; m < NN; ++m) {
        float v = A[n * NN + m];
        if (v != 0.0f) { g_colidx[off] = m; g_aval[off] = v; ++off; }
    }
}

__global__ void zero_state()
{
    int i = blockIdx.x * blockDim.x + threadIdx.x;
    const int total = BB * NN * HH;
    for (; i < total; i += gridDim.x * blockDim.x) {
        g_h0[i] = 0.0f;
        g_h1[i] = 0.0f;
    }
}

// ---------------------------------------------------------------------------
// Sparse A @ src (256 cols) for a 16-row tile -> SMEM S (row stride ldS)
// ---------------------------------------------------------------------------
__device__ __forceinline__ void spmm16(float* S, int ldS,
                                       const float* __restrict__ src,
                                       int b, int rows0)
{
    const int warp = threadIdx.x >> 5;
    const int lane = threadIdx.x & 31;
#pragma unroll
    for (int rr = 0; rr < 2; ++rr) {
        const int r    = (warp << 1) + rr;
        const int node = rows0 + r;
        const int p0 = g_rowptr[node];
        const int p1 = g_rowptr[node + 1];
        float4 a0 = make_float4(0.f, 0.f, 0.f, 0.f);
        float4 a1 = make_float4(0.f, 0.f, 0.f, 0.f);
        for (int p = p0; p < p1; ++p) {
            const int   c = g_colidx[p];
            const float v = g_aval[p];
            const float4* srow =
                reinterpret_cast<const float4*>(src + ((b << 8) + c) * HH);
            const float4 s0 = srow[lane];
            const float4 s1 = srow[lane + 32];
            a0.x += v * s0.x; a0.y += v * s0.y; a0.z += v * s0.z; a0.w += v * s0.w;
            a1.x += v * s1.x; a1.y += v * s1.y; a1.z += v * s1.z; a1.w += v * s1.w;
        }
        float4* Sp = reinterpret_cast<float4*>(S + r * ldS);
        Sp[lane]      = a0;
        Sp[lane + 32] = a1;
    }
}

// ---------------------------------------------------------------------------
// Gates kernel (z, r*h, gxc) for one layer, timestep t.
// Thread tile: 2 rows x 8 cols. Weights streamed via cp.async double buffer,
// FMAs done as packed f32x2.
// ---------------------------------------------------------------------------
template <int LAYER>
__global__ void __launch_bounds__(256, 1)
gru_gates(const float* __restrict__ x2d, const float* __restrict__ mask,
          const float* __restrict__ Wx,  const float* __restrict__ Wh,
          const float* __restrict__ bias, int t)
{
    extern __shared__ float smem[];
    const int KS = (LAYER == 1) ? 512 : 256;      // sA row stride (virtual K)
    float* sA   = smem;                            // [16][KS]
    float* sW   = smem + RPT * KS;                 // [2][KT][256]
    float* sWx0 = sW + 2 * WBUF;                   // L0 only: [6][768]
    float* sAx6 = sWx0 + DIN * H3;                 // L0 only: [16][8]

    const int tid   = threadIdx.x;
    const int b     = blockIdx.y;
    const int rows0 = blockIdx.x * RPT;
    const float* h  = (LAYER == 0) ? g_h0 : g_h1;

    // ---- sparse phase + small staging ----
    spmm16(sA, KS, h, b, rows0);                   // A @ h_layer -> k 0..255
    if (LAYER == 1) {
        spmm16(sA + 256, KS, g_h0, b, rows0);      // A @ h0      -> k 256..511
    } else {
        for (int i = tid; i < DIN * H3; i += 256) sWx0[i] = Wx[i];
        if (tid < RPT * DIN) {
            const int r = tid / DIN, d = tid % DIN;
            const int node = rows0 + r;
            const float* xt = x2d + (size_t)((b * TT + t) * NN) * DIN;
            const float* mt = mask + (size_t)(b * TT + t) * NN;
            float acc = 0.0f;
            const int p1 = g_rowptr[node + 1];
            for (int p = g_rowptr[node]; p < p1; ++p) {
                const int c = g_colidx[p];
                acc += g_aval[p] * xt[c * DIN + d] * mt[c];
            }
            sAx6[r * 8 + d] = acc;
        }
    }
    __syncthreads();

    const int tc   = tid & 31;
    const int warp = tid >> 5;
    const int r0   = warp << 1;      // 2 rows per thread
    const int c0   = tc << 3;        // 8 cols per thread

#pragma unroll 1
    for (int p = 0; p < 3; ++p) {
        // acc init with bias
        ull acc[2][4];
#pragma unroll
        for (int j = 0; j < 4; ++j) {
            float2 bv = *reinterpret_cast<const float2*>(bias + (p << 8) + c0 + (j << 1));
            const ull u = *reinterpret_cast<ull*>(&bv);
            acc[0][j] = u;
            acc[1][j] = u;
        }

        int nt;
        if (LAYER == 1) nt = (p < 2) ? 16 : 8;
        else            nt = (p < 2) ? 8  : 0;

        if (nt) {
            // weight source for virtual K-tile kt
            auto wsrc = [&](int kt) -> const float* {
                if (LAYER == 1) {
                    if (p < 2)
                        return (kt < 8) ? (Wh + kt * KT * H3 + (p << 8))
                                        : (Wx + (kt - 8) * KT * H3 + (p << 8));
                    return Wx + kt * KT * H3 + 512;
                }
                return Wh + kt * KT * H3 + (p << 8);
            };
            load_wtile(sW, wsrc(0), tid);
#pragma unroll 1
            for (int kt = 0; kt < nt; ++kt) {
                if (kt + 1 < nt) {
                    load_wtile(sW + ((kt + 1) & 1) * WBUF, wsrc(kt + 1), tid);
                    CP_WAIT1();
                } else {
                    CP_WAIT0();
                }
                __syncthreads();
                const float* buf = sW + (kt & 1) * WBUF;
                const int kbase = (LAYER == 1 && p == 2) ? (256 + kt * KT)
                                                         : (kt * KT);
                const float* sa0 = sA + r0 * KS + kbase;
                const float* sa1 = sa0 + KS;
#pragma unroll
                for (int kk = 0; kk < KT; ++kk) {
                    const float v0 = sa0[kk];
                    const float v1 = sa1[kk];
                    const ull s0 = pk2(v0, v0);
                    const ull s1 = pk2(v1, v1);
                    const float4 wa = *reinterpret_cast<const float4*>(buf + kk * 256 + c0);
                    const float4 wb = *reinterpret_cast<const float4*>(buf + kk * 256 + c0 + 4);
                    const ull* wp = reinterpret_cast<const ull*>(&wa);
                    const ull* wq = reinterpret_cast<const ull*>(&wb);
                    ffma2(acc[0][0], s0, wp[0]); ffma2(acc[0][1], s0, wp[1]);
                    ffma2(acc[0][2], s0, wq[0]); ffma2(acc[0][3], s0, wq[1]);
                    ffma2(acc[1][0], s1, wp[0]); ffma2(acc[1][1], s1, wp[1]);
                    ffma2(acc[1][2], s1, wq[0]); ffma2(acc[1][3], s1, wq[1]);
                }
                __syncthreads();
            }
        }

        if (LAYER == 0) {
            // x-path contribution (K = DIN = 6) from smem-cached Wx0
#pragma unroll
            for (int k6 = 0; k6 < DIN; ++k6) {
                const float v0 = sAx6[r0 * 8 + k6];
                const float v1 = sAx6[(r0 + 1) * 8 + k6];
                const ull s0 = pk2(v0, v0);
                const ull s1 = pk2(v1, v1);
                const float* wr = sWx0 + k6 * H3 + (p << 8) + c0;
                const float4 wa = *reinterpret_cast<const float4*>(wr);
                const float4 wb = *reinterpret_cast<const float4*>(wr + 4);
                const ull* wp = reinterpret_cast<const ull*>(&wa);
                const ull* wq = reinterpret_cast<const ull*>(&wb);
                ffma2(acc[0][0], s0, wp[0]); ffma2(acc[0][1], s0, wp[1]);
                ffma2(acc[0][2], s0, wq[0]); ffma2(acc[0][3], s0, wq[1]);
                ffma2(acc[1][0], s1, wp[0]); ffma2(acc[1][1], s1, wp[1]);
                ffma2(acc[1][2], s1, wq[0]); ffma2(acc[1][3], s1, wq[1]);
            }
        }

        // epilogue
#pragma unroll
        for (int i = 0; i < 2; ++i) {
            const int base = (((b << 8) + rows0 + r0 + i) << 8) + c0;
#pragma unroll
            for (int j = 0; j < 4; ++j) {
                const float2 g = upk2(acc[i][j]);
                const int idx = base + (j << 1);
                if (p == 0) {
                    float2 o;
                    o.x = 1.0f / (1.0f + __expf(-g.x));
                    o.y = 1.0f / (1.0f + __expf(-g.y));
                    *reinterpret_cast<float2*>(g_z + idx) = o;
                } else if (p == 1) {
                    const float2 hv = *reinterpret_cast<const float2*>(h + idx);
                    float2 o;
                    o.x = hv.x / (1.0f + __expf(-g.x));
                    o.y = hv.y / (1.0f + __expf(-g.y));
                    *reinterpret_cast<float2*>(g_rh + idx) = o;
                } else {
                    *reinterpret_cast<float2*>(g_gxc + idx) = g;
                }
            }
        }
    }
}

// ---------------------------------------------------------------------------
// Update kernel: c = tanh(gxc + (A rh)@Wh[:,512:768]); h = z*h + (1-z)*c.
// LAYER==1 also computes the output head.
// ---------------------------------------------------------------------------
template <int LAYER>
__global__ void __launch_bounds__(256, 1)
gru_update(const float* __restrict__ Wh, const float* __restrict__ Wout,
           const float* __restrict__ bout, float* __restrict__ out, int t)
{
    extern __shared__ float smem[];
    float* sA  = smem;               // [16][256]
    float* sW  = smem + RPT * 256;   // [2][KT][256]
    float* sHS = sW;                 // reuse buf0 region after streaming
    float* sWo = sW + RPT * 256;     // Wout cache (inside buf0 region)

    const int tid   = threadIdx.x;
    const int b     = blockIdx.y;
    const int rows0 = blockIdx.x * RPT;
    float* h = (LAYER == 0) ? g_h0 : g_h1;

    spmm16(sA, 256, g_rh, b, rows0);
    __syncthreads();

    const int tc   = tid & 31;
    const int warp = tid >> 5;
    const int r0   = warp << 1;
    const int c0   = tc << 3;

    ull acc[2][4];
#pragma unroll
    for (int j = 0; j < 4; ++j) { acc[0][j] = 0ull; acc[1][j] = 0ull; }

    load_wtile(sW, Wh + 512, tid);
#pragma unroll 1
    for (int kt = 0; kt < 8; ++kt) {
        if (kt < 7) {
            load_wtile(sW + ((kt + 1) & 1) * WBUF, Wh + (kt + 1) * KT * H3 + 512, tid);
            CP_WAIT1();
        } else {
            CP_WAIT0();
        }
        __syncthreads();
        const float* buf = sW + (kt & 1) * WBUF;
        const float* sa0 = sA + r0 * 256 + kt * KT;
        const float* sa1 = sa0 + 256;
#pragma unroll
        for (int kk = 0; kk < KT; ++kk) {
            const float v0 = sa0[kk];
            const float v1 = sa1[kk];
            const ull s0 = pk2(v0, v0);
            const ull s1 = pk2(v1, v1);
            const float4 wa = *reinterpret_cast<const float4*>(buf + kk * 256 + c0);
            const float4 wb = *reinterpret_cast<const float4*>(buf + kk * 256 + c0 + 4);
            const ull* wp = reinterpret_cast<const ull*>(&wa);
            const ull* wq = reinterpret_cast<const ull*>(&wb);
            ffma2(acc[0][0], s0, wp[0]); ffma2(acc[0][1], s0, wp[1]);
            ffma2(acc[0][2], s0, wq[0]); ffma2(acc[0][3], s0, wq[1]);
            ffma2(acc[1][0], s1, wp[0]); ffma2(acc[1][1], s1, wp[1]);
            ffma2(acc[1][2], s1, wq[0]); ffma2(acc[1][3], s1, wq[1]);
        }
        __syncthreads();
    }

    // epilogue: GRU state update
#pragma unroll
    for (int i = 0; i < 2; ++i) {
        const int base = (((b << 8) + rows0 + r0 + i) << 8) + c0;
#pragma unroll
        for (int j = 0; j < 4; ++j) {
            const int idx = base + (j << 1);
            const float2 a  = upk2(acc[i][j]);
            const float2 gx = *reinterpret_cast<const float2*>(g_gxc + idx);
            const float2 zz = *reinterpret_cast<const float2*>(g_z + idx);
            const float2 hv = *reinterpret_cast<const float2*>(h + idx);
            const float cx = tanhf(gx.x + a.x);
            const float cy = tanhf(gx.y + a.y);
            float2 hn;
            hn.x = zz.x * hv.x + (1.0f - zz.x) * cx;
            hn.y = zz.y * hv.y + (1.0f - zz.y) * cy;
            *reinterpret_cast<float2*>(h + idx) = hn;
            if (LAYER == 1) {
                sHS[(r0 + i) * 256 + c0 + (j << 1)]     = hn.x;
                sHS[(r0 + i) * 256 + c0 + (j << 1) + 1] = hn.y;
            }
        }
    }

    if (LAYER == 1) {
        for (int i = tid; i < HH * DOUT; i += 256) sWo[i] = Wout[i];
        __syncthreads();
        for (int idx = tid; idx < RPT * DOUT; idx += 256) {
            const int row = idx / DOUT, c9 = idx % DOUT;
            float a = bout[c9];
            const float* hr = sHS + row * 256;
#pragma unroll 8
            for (int k = 0; k < HH; ++k)
                a += hr[k] * sWo[k * DOUT + c9];
            out[(size_t)((b * TT + t) * NN + rows0 + row) * DOUT + c9] = a;
        }
    }
}

// ---------------------------------------------------------------------------
// Launch
// ---------------------------------------------------------------------------
#define GATES1_SMEM ((RPT * 512 + 2 * WBUF) * 4)                       // 98304
#define GATES0_SMEM ((RPT * 256 + 2 * WBUF + DIN * H3 + RPT * 8) * 4)  // 100864
#define UPD_SMEM    ((RPT * 256 + 2 * WBUF) * 4)                       // 81920

extern "C" void kernel_launch(void* const* d_in, const int* in_sizes, int n_in,
                              void* d_out, int out_size)
{
    const float* x2d  = (const float*)d_in[0];
    const float* mask = (const float*)d_in[1];
    const float* sadj = (const float*)d_in[2];
    const float* Wx0  = (const float*)d_in[3];
    const float* Wh0  = (const float*)d_in[4];
    const float* b0   = (const float*)d_in[5];
    const float* Wx1  = (const float*)d_in[6];
    const float* Wh1  = (const float*)d_in[7];
    const float* b1   = (const float*)d_in[8];
    const float* Wout = (const float*)d_in[9];
    const float* bout = (const float*)d_in[10];
    float* out = (float*)d_out;

    cudaFuncSetAttribute(gru_gates<0>,  cudaFuncAttributeMaxDynamicSharedMemorySize, GATES0_SMEM);
    cudaFuncSetAttribute(gru_gates<1>,  cudaFuncAttributeMaxDynamicSharedMemorySize, GATES1_SMEM);
    cudaFuncSetAttribute(gru_update<0>, cudaFuncAttributeMaxDynamicSharedMemorySize, UPD_SMEM);
    cudaFuncSetAttribute(gru_update<1>, cudaFuncAttributeMaxDynamicSharedMemorySize, UPD_SMEM);

    build_csr<<<1, 256>>>(sadj);
    zero_state<<<256, 256>>>();

    dim3 grid(TILES, BB);
    for (int t = 0; t < TT; ++t) {
        gru_gates<0> <<<grid, 256, GATES0_SMEM>>>(x2d, mask, Wx0, Wh0, b0, t);
        gru_update<0><<<grid, 256, UPD_SMEM>>>(Wh0, Wout, bout, out, t);
        gru_gates<1> <<<grid, 256, GATES1_SMEM>>>(x2d, mask, Wx1, Wh1, b1, t);
        gru_update<1><<<grid, 256, UPD_SMEM>>>(Wh1, Wout, bout, out, t);
    }
}

// round 4
// speedup vs baseline: 1.3852x; 1.0009x over previous
#include <cuda_runtime.h>
#include <math.h>
#include <stdint.h>

// Problem constants
#define BB   8
#define TT   64
#define NN   256
#define HH   256
#define DIN  6
#define DOUT 9
#define H3   768
#define RPT  16                 // rows (nodes) per CTA tile
#define TILES (NN / RPT)        // 16
#define KT   32                 // K-tile depth for weight streaming
#define WBUF (KT * 256)         // floats per weight buffer (8192)

typedef unsigned long long ull;

// ---------------------------------------------------------------------------
// Device scratch (no allocations allowed)
// ---------------------------------------------------------------------------
__device__ float g_h0 [BB * NN * HH];
__device__ float g_h1 [BB * NN * HH];
__device__ float g_z  [BB * NN * HH];
__device__ float g_rh [BB * NN * HH];
__device__ float g_gxc[BB * NN * HH];
__device__ int   g_rowptr[NN + 1];
__device__ int   g_colidx[NN * NN];
__device__ float g_aval  [NN * NN];

// ---------------------------------------------------------------------------
// Helpers: packed f32x2 FMA, cp.async
// ---------------------------------------------------------------------------
__device__ __forceinline__ ull pk2(float x, float y) {
    float2 t = make_float2(x, y);
    return *reinterpret_cast<ull*>(&t);
}
__device__ __forceinline__ float2 upk2(ull u) {
    return *reinterpret_cast<float2*>(&u);
}
__device__ __forceinline__ void ffma2(ull& c, ull a, ull b) {
    asm("fma.rn.f32x2 %0, %1, %2, %0;" : "+l"(c) : "l"(a), "l"(b));
}
__device__ __forceinline__ uint32_t sptr(const void* p) {
    return (uint32_t)__cvta_generic_to_shared(p);
}
__device__ __forceinline__ void cp16(uint32_t s, const void* g) {
    asm volatile("cp.async.ca.shared.global [%0], [%1], 16;" :: "r"(s), "l"(g));
}
#define CP_COMMIT() asm volatile("cp.async.commit_group;")
#define CP_WAIT1()  asm volatile("cp.async.wait_group 1;")
#define CP_WAIT0()  asm volatile("cp.async.wait_group 0;")

// Load one weight K-tile [KT][256] (row stride H3 in global) into smem buf.
__device__ __forceinline__ void load_wtile(float* buf, const float* __restrict__ src,
                                           int tid) {
#pragma unroll
    for (int i = 0; i < 8; ++i) {
        const int f   = tid + (i << 8);      // float4 index 0..2047
        const int row = f >> 6;
        const int c4  = f & 63;
        cp16(sptr(buf + row * 256 + (c4 << 2)), src + row * H3 + (c4 << 2));
    }
    CP_COMMIT();
}

// ---------------------------------------------------------------------------
// Prologue kernels
// ---------------------------------------------------------------------------
__global__ void build_csr(const float* __restrict__ A)
{
    __shared__ int cnt[NN];
    const int n = threadIdx.x;
    int c = 0;
    for (int m = 0; m < NN; ++m)
        if (A[n * NN + m] != 0.0f) ++c;
    cnt[n] = c;
    __syncthreads();
    if (n == 0) {
        int s = 0;
        for (int i = 0; i < NN; ++i) { g_rowptr[i] = s; s += cnt[i]; }
        g_rowptr[NN] = s;
    }
    __syncthreads();
    int off = g_rowptr[n];
    for (int m = 0; m < NN; ++m) {
        float v = A[n * NN + m];
        if (v != 0.0f) { g_colidx[off] = m; g_aval[off] = v; ++off; }
    }
}

__global__ void zero_state()
{
    int i = blockIdx.x * blockDim.x + threadIdx.x;
    const int total = BB * NN * HH;
    for (; i < total; i += gridDim.x * blockDim.x) {
        g_h0[i] = 0.0f;
        g_h1[i] = 0.0f;
    }
}

// ---------------------------------------------------------------------------
// Sparse A @ src (256 cols) for a 16-row tile -> SMEM S (row stride ldS)
// ---------------------------------------------------------------------------
__device__ __forceinline__ void spmm16(float* S, int ldS,
                                       const float* __restrict__ src,
                                       int b, int rows0)
{
    const int warp = threadIdx.x >> 5;
    const int lane = threadIdx.x & 31;
#pragma unroll
    for (int rr = 0; rr < 2; ++rr) {
        const int r    = (warp << 1) + rr;
        const int node = rows0 + r;
        const int p0 = g_rowptr[node];
        const int p1 = g_rowptr[node + 1];
        float4 a0 = make_float4(0.f, 0.f, 0.f, 0.f);
        float4 a1 = make_float4(0.f, 0.f, 0.f, 0.f);
        for (int p = p0; p < p1; ++p) {
            const int   c = g_colidx[p];
            const float v = g_aval[p];
            const float4* srow =
                reinterpret_cast<const float4*>(src + ((b << 8) + c) * HH);
            const float4 s0 = srow[lane];
            const float4 s1 = srow[lane + 32];
            a0.x += v * s0.x; a0.y += v * s0.y; a0.z += v * s0.z; a0.w += v * s0.w;
            a1.x += v * s1.x; a1.y += v * s1.y; a1.z += v * s1.z; a1.w += v * s1.w;
        }
        float4* Sp = reinterpret_cast<float4*>(S + r * ldS);
        Sp[lane]      = a0;
        Sp[lane + 32] = a1;
    }
}

// ---------------------------------------------------------------------------
// Gates kernel (z, r*h, gxc) for one layer, timestep t.
// Thread tile: 2 rows x 8 cols. Weights streamed via cp.async double buffer,
// FMAs done as packed f32x2.
// ---------------------------------------------------------------------------
template <int LAYER>
__global__ void __launch_bounds__(256, 1)
gru_gates(const float* __restrict__ x2d, const float* __restrict__ mask,
          const float* __restrict__ Wx,  const float* __restrict__ Wh,
          const float* __restrict__ bias, int t)
{
    extern __shared__ float smem[];
    const int KS = (LAYER == 1) ? 512 : 256;      // sA row stride (virtual K)
    float* sA   = smem;                            // [16][KS]
    float* sW   = smem + RPT * KS;                 // [2][KT][256]
    float* sWx0 = sW + 2 * WBUF;                   // L0 only: [6][768]
    float* sAx6 = sWx0 + DIN * H3;                 // L0 only: [16][8]

    const int tid   = threadIdx.x;
    const int b     = blockIdx.y;
    const int rows0 = blockIdx.x * RPT;
    const float* h  = (LAYER == 0) ? g_h0 : g_h1;

    // ---- sparse phase + small staging ----
    spmm16(sA, KS, h, b, rows0);                   // A @ h_layer -> k 0..255
    if (LAYER == 1) {
        spmm16(sA + 256, KS, g_h0, b, rows0);      // A @ h0      -> k 256..511
    } else {
        for (int i = tid; i < DIN * H3; i += 256) sWx0[i] = Wx[i];
        if (tid < RPT * DIN) {
            const int r = tid / DIN, d = tid % DIN;
            const int node = rows0 + r;
            const float* xt = x2d + (size_t)((b * TT + t) * NN) * DIN;
            const float* mt = mask + (size_t)(b * TT + t) * NN;
            float acc = 0.0f;
            const int p1 = g_rowptr[node + 1];
            for (int p = g_rowptr[node]; p < p1; ++p) {
                const int c = g_colidx[p];
                acc += g_aval[p] * xt[c * DIN + d] * mt[c];
            }
            sAx6[r * 8 + d] = acc;
        }
    }
    __syncthreads();

    const int tc   = tid & 31;
    const int warp = tid >> 5;
    const int r0   = warp << 1;      // 2 rows per thread
    const int c0   = tc << 3;        // 8 cols per thread

#pragma unroll 1
    for (int p = 0; p < 3; ++p) {
        // acc init with bias
        ull acc[2][4];
#pragma unroll
        for (int j = 0; j < 4; ++j) {
            float2 bv = *reinterpret_cast<const float2*>(bias + (p << 8) + c0 + (j << 1));
            const ull u = *reinterpret_cast<ull*>(&bv);
            acc[0][j] = u;
            acc[1][j] = u;
        }

        int nt;
        if (LAYER == 1) nt = (p < 2) ? 16 : 8;
        else            nt = (p < 2) ? 8  : 0;

        if (nt) {
            // weight source for virtual K-tile kt
            auto wsrc = [&](int kt) -> const float* {
                if (LAYER == 1) {
                    if (p < 2)
                        return (kt < 8) ? (Wh + kt * KT * H3 + (p << 8))
                                        : (Wx + (kt - 8) * KT * H3 + (p << 8));
                    return Wx + kt * KT * H3 + 512;
                }
                return Wh + kt * KT * H3 + (p << 8);
            };
            load_wtile(sW, wsrc(0), tid);
#pragma unroll 1
            for (int kt = 0; kt < nt; ++kt) {
                if (kt + 1 < nt) {
                    load_wtile(sW + ((kt + 1) & 1) * WBUF, wsrc(kt + 1), tid);
                    CP_WAIT1();
                } else {
                    CP_WAIT0();
                }
                __syncthreads();
                const float* buf = sW + (kt & 1) * WBUF;
                const int kbase = (LAYER == 1 && p == 2) ? (256 + kt * KT)
                                                         : (kt * KT);
                const float* sa0 = sA + r0 * KS + kbase;
                const float* sa1 = sa0 + KS;
#pragma unroll
                for (int kk = 0; kk < KT; ++kk) {
                    const float v0 = sa0[kk];
                    const float v1 = sa1[kk];
                    const ull s0 = pk2(v0, v0);
                    const ull s1 = pk2(v1, v1);
                    const float4 wa = *reinterpret_cast<const float4*>(buf + kk * 256 + c0);
                    const float4 wb = *reinterpret_cast<const float4*>(buf + kk * 256 + c0 + 4);
                    const ull* wp = reinterpret_cast<const ull*>(&wa);
                    const ull* wq = reinterpret_cast<const ull*>(&wb);
                    ffma2(acc[0][0], s0, wp[0]); ffma2(acc[0][1], s0, wp[1]);
                    ffma2(acc[0][2], s0, wq[0]); ffma2(acc[0][3], s0, wq[1]);
                    ffma2(acc[1][0], s1, wp[0]); ffma2(acc[1][1], s1, wp[1]);
                    ffma2(acc[1][2], s1, wq[0]); ffma2(acc[1][3], s1, wq[1]);
                }
                __syncthreads();
            }
        }

        if (LAYER == 0) {
            // x-path contribution (K = DIN = 6) from smem-cached Wx0
#pragma unroll
            for (int k6 = 0; k6 < DIN; ++k6) {
                const float v0 = sAx6[r0 * 8 + k6];
                const float v1 = sAx6[(r0 + 1) * 8 + k6];
                const ull s0 = pk2(v0, v0);
                const ull s1 = pk2(v1, v1);
                const float* wr = sWx0 + k6 * H3 + (p << 8) + c0;
                const float4 wa = *reinterpret_cast<const float4*>(wr);
                const float4 wb = *reinterpret_cast<const float4*>(wr + 4);
                const ull* wp = reinterpret_cast<const ull*>(&wa);
                const ull* wq = reinterpret_cast<const ull*>(&wb);
                ffma2(acc[0][0], s0, wp[0]); ffma2(acc[0][1], s0, wp[1]);
                ffma2(acc[0][2], s0, wq[0]); ffma2(acc[0][3], s0, wq[1]);
                ffma2(acc[1][0], s1, wp[0]); ffma2(acc[1][1], s1, wp[1]);
                ffma2(acc[1][2], s1, wq[0]); ffma2(acc[1][3], s1, wq[1]);
            }
        }

        // epilogue
#pragma unroll
        for (int i = 0; i < 2; ++i) {
            const int base = (((b << 8) + rows0 + r0 + i) << 8) + c0;
#pragma unroll
            for (int j = 0; j < 4; ++j) {
                const float2 g = upk2(acc[i][j]);
                const int idx = base + (j << 1);
                if (p == 0) {
                    float2 o;
                    o.x = 1.0f / (1.0f + __expf(-g.x));
                    o.y = 1.0f / (1.0f + __expf(-g.y));
                    *reinterpret_cast<float2*>(g_z + idx) = o;
                } else if (p == 1) {
                    const float2 hv = *reinterpret_cast<const float2*>(h + idx);
                    float2 o;
                    o.x = hv.x / (1.0f + __expf(-g.x));
                    o.y = hv.y / (1.0f + __expf(-g.y));
                    *reinterpret_cast<float2*>(g_rh + idx) = o;
                } else {
                    *reinterpret_cast<float2*>(g_gxc + idx) = g;
                }
            }
        }
    }
}

// ---------------------------------------------------------------------------
// Update kernel: c = tanh(gxc + (A rh)@Wh[:,512:768]); h = z*h + (1-z)*c.
// LAYER==1 also computes the output head.
// ---------------------------------------------------------------------------
template <int LAYER>
__global__ void __launch_bounds__(256, 1)
gru_update(const float* __restrict__ Wh, const float* __restrict__ Wout,
           const float* __restrict__ bout, float* __restrict__ out, int t)
{
    extern __shared__ float smem[];
    float* sA  = smem;               // [16][256]
    float* sW  = smem + RPT * 256;   // [2][KT][256]
    float* sHS = sW;                 // reuse buf0 region after streaming
    float* sWo = sW + RPT * 256;     // Wout cache (inside buf0 region)

    const int tid   = threadIdx.x;
    const int b     = blockIdx.y;
    const int rows0 = blockIdx.x * RPT;
    float* h = (LAYER == 0) ? g_h0 : g_h1;

    spmm16(sA, 256, g_rh, b, rows0);
    __syncthreads();

    const int tc   = tid & 31;
    const int warp = tid >> 5;
    const int r0   = warp << 1;
    const int c0   = tc << 3;

    ull acc[2][4];
#pragma unroll
    for (int j = 0; j < 4; ++j) { acc[0][j] = 0ull; acc[1][j] = 0ull; }

    load_wtile(sW, Wh + 512, tid);
#pragma unroll 1
    for (int kt = 0; kt < 8; ++kt) {
        if (kt < 7) {
            load_wtile(sW + ((kt + 1) & 1) * WBUF, Wh + (kt + 1) * KT * H3 + 512, tid);
            CP_WAIT1();
        } else {
            CP_WAIT0();
        }
        __syncthreads();
        const float* buf = sW + (kt & 1) * WBUF;
        const float* sa0 = sA + r0 * 256 + kt * KT;
        const float* sa1 = sa0 + 256;
#pragma unroll
        for (int kk = 0; kk < KT; ++kk) {
            const float v0 = sa0[kk];
            const float v1 = sa1[kk];
            const ull s0 = pk2(v0, v0);
            const ull s1 = pk2(v1, v1);
            const float4 wa = *reinterpret_cast<const float4*>(buf + kk * 256 + c0);
            const float4 wb = *reinterpret_cast<const float4*>(buf + kk * 256 + c0 + 4);
            const ull* wp = reinterpret_cast<const ull*>(&wa);
            const ull* wq = reinterpret_cast<const ull*>(&wb);
            ffma2(acc[0][0], s0, wp[0]); ffma2(acc[0][1], s0, wp[1]);
            ffma2(acc[0][2], s0, wq[0]); ffma2(acc[0][3], s0, wq[1]);
            ffma2(acc[1][0], s1, wp[0]); ffma2(acc[1][1], s1, wp[1]);
            ffma2(acc[1][2], s1, wq[0]); ffma2(acc[1][3], s1, wq[1]);
        }
        __syncthreads();
    }

    // epilogue: GRU state update
#pragma unroll
    for (int i = 0; i < 2; ++i) {
        const int base = (((b << 8) + rows0 + r0 + i) << 8) + c0;
#pragma unroll
        for (int j = 0; j < 4; ++j) {
            const int idx = base + (j << 1);
            const float2 a  = upk2(acc[i][j]);
            const float2 gx = *reinterpret_cast<const float2*>(g_gxc + idx);
            const float2 zz = *reinterpret_cast<const float2*>(g_z + idx);
            const float2 hv = *reinterpret_cast<const float2*>(h + idx);
            const float cx = tanhf(gx.x + a.x);
            const float cy = tanhf(gx.y + a.y);
            float2 hn;
            hn.x = zz.x * hv.x + (1.0f - zz.x) * cx;
            hn.y = zz.y * hv.y + (1.0f - zz.y) * cy;
            *reinterpret_cast<float2*>(h + idx) = hn;
            if (LAYER == 1) {
                sHS[(r0 + i) * 256 + c0 + (j << 1)]     = hn.x;
                sHS[(r0 + i) * 256 + c0 + (j << 1) + 1] = hn.y;
            }
        }
    }

    if (LAYER == 1) {
        for (int i = tid; i < HH * DOUT; i += 256) sWo[i] = Wout[i];
        __syncthreads();
        for (int idx = tid; idx < RPT * DOUT; idx += 256) {
            const int row = idx / DOUT, c9 = idx % DOUT;
            float a = bout[c9];
            const float* hr = sHS + row * 256;
#pragma unroll 8
            for (int k = 0; k < HH; ++k)
                a += hr[k] * sWo[k * DOUT + c9];
            out[(size_t)((b * TT + t) * NN + rows0 + row) * DOUT + c9] = a;
        }
    }
}

// ---------------------------------------------------------------------------
// Launch
// ---------------------------------------------------------------------------
#define GATES1_SMEM ((RPT * 512 + 2 * WBUF) * 4)                       // 98304
#define GATES0_SMEM ((RPT * 256 + 2 * WBUF + DIN * H3 + RPT * 8) * 4)  // 100864
#define UPD_SMEM    ((RPT * 256 + 2 * WBUF) * 4)                       // 81920

extern "C" void kernel_launch(void* const* d_in, const int* in_sizes, int n_in,
                              void* d_out, int out_size)
{
    const float* x2d  = (const float*)d_in[0];
    const float* mask = (const float*)d_in[1];
    const float* sadj = (const float*)d_in[2];
    const float* Wx0  = (const float*)d_in[3];
    const float* Wh0  = (const float*)d_in[4];
    const float* b0   = (const float*)d_in[5];
    const float* Wx1  = (const float*)d_in[6];
    const float* Wh1  = (const float*)d_in[7];
    const float* b1   = (const float*)d_in[8];
    const float* Wout = (const float*)d_in[9];
    const float* bout = (const float*)d_in[10];
    float* out = (float*)d_out;

    cudaFuncSetAttribute(gru_gates<0>,  cudaFuncAttributeMaxDynamicSharedMemorySize, GATES0_SMEM);
    cudaFuncSetAttribute(gru_gates<1>,  cudaFuncAttributeMaxDynamicSharedMemorySize, GATES1_SMEM);
    cudaFuncSetAttribute(gru_update<0>, cudaFuncAttributeMaxDynamicSharedMemorySize, UPD_SMEM);
    cudaFuncSetAttribute(gru_update<1>, cudaFuncAttributeMaxDynamicSharedMemorySize, UPD_SMEM);

    build_csr<<<1, 256>>>(sadj);
    zero_state<<<256, 256>>>();

    dim3 grid(TILES, BB);
    for (int t = 0; t < TT; ++t) {
        gru_gates<0> <<<grid, 256, GATES0_SMEM>>>(x2d, mask, Wx0, Wh0, b0, t);
        gru_update<0><<<grid, 256, UPD_SMEM>>>(Wh0, Wout, bout, out, t);
        gru_gates<1> <<<grid, 256, GATES1_SMEM>>>(x2d, mask, Wx1, Wh1, b1, t);
        gru_update<1><<<grid, 256, UPD_SMEM>>>(Wh1, Wout, bout, out, t);
    }
}